// round 8
// baseline (speedup 1.0000x reference)
#include <cuda_runtime.h>
#include <cuda_bf16.h>
#include <math.h>
#include <stdint.h>

// ---------------- problem constants ----------------
#define BATCHN  16
#define LSEQ    2048
#define INDIM   64
#define HID     256
#define STATE   256
#define MLPD    1024
#define OUTD    128
#define NL      4
#define BL      (BATCHN * LSEQ)      // 32768 rows
#define CL      128                  // scan chunk length
#define NC      (LSEQ / CL)          // 16 chunks

// smem: CTA tile 128(M) x 128(N), K chunk 32, bf16 hi/lo tiles, 80B pitch
#define LDS_ROW   80
#define TILE_B    10240              // 128 rows * 80
#define T_AH      0
#define T_AL      10240
#define T_BH      20480
#define T_BL      30720
#define STAGE_B   40960
#define SMEM_BYTES (2 * STAGE_B)     // 81920 -> 2 CTAs/SM

// ---------------- device scratch (static, no allocations) ----------------
__device__ float g_h  [BL * HID];
__device__ float g_y  [BL * HID];
__device__ float g_sre[BL * STATE];
__device__ float g_sim[BL * STATE];
__device__ float g_cre[BATCHN * NC * STATE];
__device__ float g_cim[BATCHN * NC * STATE];
__device__ float g_ire[BATCHN * NC * STATE];
__device__ float g_iim[BATCHN * NC * STATE];
__device__ float g_lamre[NL * STATE];
__device__ float g_lamim[NL * STATE];
__device__ float g_eg   [NL * STATE];

// bf16 hi/lo splits (inputs, weights, activations)
__device__ uint16_t g_x_h [BL * INDIM],  g_x_l [BL * INDIM];
__device__ uint16_t g_eW_h[HID * INDIM], g_eW_l[HID * INDIM];
__device__ uint16_t g_Br_h[NL*STATE*HID], g_Br_l[NL*STATE*HID];
__device__ uint16_t g_Bi_h[NL*STATE*HID], g_Bi_l[NL*STATE*HID];
__device__ uint16_t g_Cr_h[NL*HID*STATE], g_Cr_l[NL*HID*STATE];
__device__ uint16_t g_nCi_h[NL*HID*STATE], g_nCi_l[NL*HID*STATE];
__device__ uint16_t g_Wh_h[NL*MLPD*STATE], g_Wh_l[NL*MLPD*STATE];
__device__ uint16_t g_Wo_h[NL*HID*MLPD],  g_Wo_l[NL*HID*MLPD];
__device__ uint16_t g_oW_h[OUTD*HID],     g_oW_l[OUTD*HID];
__device__ uint16_t g_h_h [BL * HID],  g_h_l [BL * HID];
__device__ uint16_t g_y_h [BL * HID],  g_y_l [BL * HID];
__device__ uint16_t g_sr_h[BL * STATE], g_sr_l[BL * STATE];
__device__ uint16_t g_si_h[BL * STATE], g_si_l[BL * STATE];
__device__ uint16_t g_z_h [BL * MLPD],  g_z_l [BL * MLPD];

// ---------------- PTX helpers ----------------
__device__ __forceinline__ uint32_t smem_u32(const void* p) {
    uint32_t a;
    asm("{ .reg .u64 t; cvta.to.shared.u64 t, %1; cvt.u32.u64 %0, t; }"
        : "=r"(a) : "l"(p));
    return a;
}
// pack two fp32 -> bf16x2 (x low half, y high half)
__device__ __forceinline__ uint32_t cvt2(float x, float y) {
    uint32_t r;
    asm("cvt.rn.bf16x2.f32 %0, %1, %2;" : "=r"(r) : "f"(y), "f"(x));
    return r;
}
__device__ __forceinline__ void cpa16(uint32_t dst, const void* src) {
    asm volatile("cp.async.cg.shared.global [%0], [%1], 16;"
                 :: "r"(dst), "l"(src) : "memory");
}
#define LDSM4(r0, r1, r2, r3, addr) \
    asm volatile("ldmatrix.sync.aligned.m8n8.x4.shared.b16 {%0,%1,%2,%3}, [%4];" \
                 : "=r"(r0), "=r"(r1), "=r"(r2), "=r"(r3) : "r"(addr))
#define MMA_BF16(d, a, b) \
    asm volatile("mma.sync.aligned.m16n8k16.row.col.f32.bf16.bf16.f32 " \
                 "{%0,%1,%2,%3},{%4,%5,%6,%7},{%8,%9},{%0,%1,%2,%3};" \
                 : "+f"((d)[0]), "+f"((d)[1]), "+f"((d)[2]), "+f"((d)[3]) \
                 : "r"((a)[0]), "r"((a)[1]), "r"((a)[2]), "r"((a)[3]), \
                   "r"((b)[0]), "r"((b)[1]))

// ---------------- prep kernels ----------------
__global__ void prep_kernel(const float* __restrict__ nu,
                            const float* __restrict__ th,
                            const float* __restrict__ gl) {
    const int l = blockIdx.x, s = threadIdx.x;
    const int idx = l * STATE + s;
    const float enu = expf(nu[idx]);
    const float eth = expf(th[idx]);
    const float mag = expf(-enu);
    g_lamre[idx] = mag * cosf(eth);
    g_lamim[idx] = mag * sinf(eth);
    g_eg[idx]    = expf(gl[idx]);
}

// split fp32 -> bf16 hi/lo (with optional sign flip)
__global__ void cvt_split(const float* __restrict__ src,
                          uint16_t* __restrict__ hi, uint16_t* __restrict__ lo,
                          float sgn) {
    const int i = blockIdx.x * 256 + threadIdx.x;
    const float v = sgn * src[i];
    const __nv_bfloat16 h = __float2bfloat16(v);
    hi[i] = __bfloat16_as_ushort(h);
    lo[i] = __bfloat16_as_ushort(__float2bfloat16(v - __bfloat162float(h)));
}

// ---------------- chunked complex diagonal scan ----------------
__global__ void scan_pass1(int l) {
    const int s = threadIdx.x, c = blockIdx.x, b = blockIdx.y;
    const float lr = g_lamre[l * STATE + s];
    const float li = g_lamim[l * STATE + s];
    size_t idx = ((size_t)(b * LSEQ + c * CL)) * STATE + s;
    float ar = 0.f, ai = 0.f;
    for (int t = 0; t < CL; ++t, idx += STATE) {
        const float br = g_sre[idx], bi = g_sim[idx];
        const float nr = fmaf(lr, ar, fmaf(-li, ai, br));
        const float ni = fmaf(lr, ai, fmaf( li, ar, bi));
        ar = nr; ai = ni;
        g_sre[idx] = ar; g_sim[idx] = ai;
    }
    const int ci = (b * NC + c) * STATE + s;
    g_cre[ci] = ar; g_cim[ci] = ai;
}

__global__ void scan_pass2(int l, const float* __restrict__ nu,
                           const float* __restrict__ th) {
    const int s = threadIdx.x, b = blockIdx.x;
    const float enu = expf(nu[l * STATE + s]);
    const float eth = expf(th[l * STATE + s]);
    const float r   = expf(-(float)CL * enu);
    const float ang = (float)CL * eth;
    const float Ar = r * cosf(ang), Ai = r * sinf(ang);
    float pr = 0.f, pi = 0.f;
    for (int c = 0; c < NC; ++c) {
        const int ci = (b * NC + c) * STATE + s;
        g_ire[ci] = pr; g_iim[ci] = pi;
        const float cr = g_cre[ci], cii = g_cim[ci];
        const float nr = fmaf(Ar, pr, fmaf(-Ai, pi, cr));
        const float ni = fmaf(Ar, pi, fmaf( Ai, pr, cii));
        pr = nr; pi = ni;
    }
}

// pass3: apply incoming-prefix fixup AND emit bf16 hi/lo of final states
__global__ void scan_pass3(int l) {
    const int s = threadIdx.x, c = blockIdx.x, b = blockIdx.y;
    const int ci = (b * NC + c) * STATE + s;
    const float fr = g_ire[ci], fi = g_iim[ci];   // zero for c==0
    const float lr = g_lamre[l * STATE + s];
    const float li = g_lamim[l * STATE + s];
    float pr = lr, pi = li;
    size_t idx = ((size_t)(b * LSEQ + c * CL)) * STATE + s;
    for (int t = 0; t < CL; ++t, idx += STATE) {
        const float vr = fmaf(pr, fr, fmaf(-pi, fi, g_sre[idx]));
        const float vi = fmaf(pr, fi, fmaf( pi, fr, g_sim[idx]));
        const __nv_bfloat16 hr = __float2bfloat16(vr);
        const __nv_bfloat16 hi = __float2bfloat16(vi);
        g_sr_h[idx] = __bfloat16_as_ushort(hr);
        g_sr_l[idx] = __bfloat16_as_ushort(__float2bfloat16(vr - __bfloat162float(hr)));
        g_si_h[idx] = __bfloat16_as_ushort(hi);
        g_si_l[idx] = __bfloat16_as_ushort(__float2bfloat16(vi - __bfloat162float(hi)));
        const float nr = pr * lr - pi * li;
        const float ni = fmaf(pr, li, pi * lr);
        pr = nr; pi = ni;
    }
}

// ---------------- bf16x3 warp-MMA GEMM, cp.async pipelined -------------------
// C = A(MxK) @ W(NxK)^T (+ optional second product), A/W pre-split bf16 hi/lo.
// CTA tile 128x128; 8 warps 4(M)x2(N); warp tile 32x64; K chunk 32; 2 stages.
// EPI: 0=+bias 1=gelu(x+bias) 2=+bias+res 3=*scale[col] 4=+scale[col]*res
template <int EPI, bool DUAL, bool WF32, bool WBF>
__global__ void __launch_bounds__(256, 2)
mma_gemm(const uint16_t* __restrict__ Ah, const uint16_t* __restrict__ Al,
         const uint16_t* __restrict__ Wh_, const uint16_t* __restrict__ Wl_,
         const uint16_t* __restrict__ A2h, const uint16_t* __restrict__ A2l,
         const uint16_t* __restrict__ W2h, const uint16_t* __restrict__ W2l,
         float* __restrict__ Of, uint16_t* __restrict__ Oh, uint16_t* __restrict__ Ol,
         int N, int K,
         const float* __restrict__ bias, const float* __restrict__ scale,
         const float* __restrict__ res)
{
    extern __shared__ char smem[];
    const uint32_t sb = smem_u32(smem);
    const int tid  = threadIdx.x;
    const int lane = tid & 31, wid = tid >> 5;
    const int wm = wid & 3, wn = wid >> 2;          // 4(M) x 2(N)
    const int row0 = blockIdx.y * 128, col0 = blockIdx.x * 128;

    float acc[2][8][4];
#pragma unroll
    for (int mt = 0; mt < 2; ++mt)
#pragma unroll
        for (int nt = 0; nt < 8; ++nt)
#pragma unroll
            for (int e = 0; e < 4; ++e) acc[mt][nt][e] = 0.f;

    const int KC   = K >> 5;
    const int CTOT = DUAL ? 2 * KC : KC;

    const uint32_t aOff = (uint32_t)((wm * 32 + (lane & 15)) * LDS_ROW + ((lane >> 4) << 4));
    const uint32_t bOff = (uint32_t)((wn * 64 + (((lane >> 4) << 3) | (lane & 7))) * LDS_ROW
                                     + (((lane >> 3) & 1) << 4));

    // issue cp.async for chunk c into stage c&1, always commit a group
    auto issue = [&](int c) {
        if (c < CTOT) {
            const int pass = (DUAL && c >= KC) ? 1 : 0;
            const int k0 = (c - (pass ? KC : 0)) << 5;
            const uint16_t* ah = pass ? A2h : Ah;
            const uint16_t* al = pass ? A2l : Al;
            const uint16_t* wh = pass ? W2h : Wh_;
            const uint16_t* wl = pass ? W2l : Wl_;
            const uint32_t st = sb + (uint32_t)(c & 1) * STAGE_B;
#pragma unroll
            for (int i = 0; i < 8; ++i) {
                const int tile = i >> 1;                    // compile-time
                const int slot = ((i & 1) << 8) + tid;      // 0..511
                const int row = slot >> 2, c16 = slot & 3;
                const uint32_t dst = st + (uint32_t)(tile * TILE_B)
                                   + (uint32_t)(row * LDS_ROW + c16 * 16);
                const uint16_t* src;
                if      (tile == 0) src = ah + (size_t)(row0 + row) * K + k0 + c16 * 8;
                else if (tile == 1) src = al + (size_t)(row0 + row) * K + k0 + c16 * 8;
                else if (tile == 2) src = wh + (size_t)(col0 + row) * K + k0 + c16 * 8;
                else                src = wl + (size_t)(col0 + row) * K + k0 + c16 * 8;
                cpa16(dst, src);
            }
        }
        asm volatile("cp.async.commit_group;" ::: "memory");
    };

    issue(0);
    issue(1);

    for (int c = 0; c < CTOT; ++c) {
        asm volatile("cp.async.wait_group 1;" ::: "memory");
        __syncthreads();
        const uint32_t st = sb + (uint32_t)(c & 1) * STAGE_B;
#pragma unroll
        for (int ks = 0; ks < 2; ++ks) {
            const uint32_t kb = (uint32_t)(ks * 32);
            uint32_t ahf[2][4], alf[2][4];
#pragma unroll
            for (int mt = 0; mt < 2; ++mt) {
                const uint32_t ad = st + aOff + (uint32_t)(mt * 16 * LDS_ROW) + kb;
                LDSM4(ahf[mt][0], ahf[mt][1], ahf[mt][2], ahf[mt][3], ad + T_AH);
                LDSM4(alf[mt][0], alf[mt][1], alf[mt][2], alf[mt][3], ad + T_AL);
            }
#pragma unroll
            for (int np = 0; np < 4; ++np) {
                uint32_t bh[2][2], bl[2][2];
                const uint32_t bd = st + bOff + (uint32_t)(np * 16 * LDS_ROW) + kb;
                LDSM4(bh[0][0], bh[0][1], bh[1][0], bh[1][1], bd + T_BH);
                LDSM4(bl[0][0], bl[0][1], bl[1][0], bl[1][1], bd + T_BL);
#pragma unroll
                for (int mt = 0; mt < 2; ++mt)
#pragma unroll
                    for (int j = 0; j < 2; ++j) {
                        MMA_BF16(acc[mt][np * 2 + j], ahf[mt], bh[j]);
                        MMA_BF16(acc[mt][np * 2 + j], alf[mt], bh[j]);
                        MMA_BF16(acc[mt][np * 2 + j], ahf[mt], bl[j]);
                    }
            }
        }
        __syncthreads();
        issue(c + 2);
    }

    // ---- epilogue: fused op, write fp32 and/or bf16 hi/lo ----
#pragma unroll
    for (int mt = 0; mt < 2; ++mt) {
#pragma unroll
        for (int nt = 0; nt < 8; ++nt) {
            const int rA = row0 + wm * 32 + mt * 16 + (lane >> 2);
            const int cc = col0 + wn * 64 + nt * 8 + (lane & 3) * 2;
#pragma unroll
            for (int half = 0; half < 2; ++half) {
                const int r = rA + half * 8;
                const size_t go = (size_t)r * N + cc;
                float v0 = acc[mt][nt][half * 2 + 0];
                float v1 = acc[mt][nt][half * 2 + 1];
                if (EPI == 0) { v0 += bias[cc]; v1 += bias[cc + 1]; }
                if (EPI == 1) {
                    const float t0 = v0 + bias[cc], t1 = v1 + bias[cc + 1];
                    v0 = 0.5f * t0 * (1.0f + erff(t0 * 0.7071067811865476f));
                    v1 = 0.5f * t1 * (1.0f + erff(t1 * 0.7071067811865476f));
                }
                if (EPI == 2) { v0 += bias[cc]     + res[go];
                                v1 += bias[cc + 1] + res[go + 1]; }
                if (EPI == 3) { v0 *= scale[cc]; v1 *= scale[cc + 1]; }
                if (EPI == 4) { v0 = fmaf(scale[cc],     res[go],     v0);
                                v1 = fmaf(scale[cc + 1], res[go + 1], v1); }
                if (WF32) *(float2*)&Of[go] = make_float2(v0, v1);
                if (WBF) {
                    const uint32_t hp = cvt2(v0, v1);
                    const float h0 = __uint_as_float(hp << 16);
                    const float h1 = __uint_as_float(hp & 0xFFFF0000u);
                    *(uint32_t*)(Oh + go) = hp;
                    *(uint32_t*)(Ol + go) = cvt2(v0 - h0, v1 - h1);
                }
            }
        }
    }
}

// ---------------- launch ----------------
extern "C" void kernel_launch(void* const* d_in, const int* in_sizes, int n_in,
                              void* d_out, int out_size)
{
    (void)in_sizes; (void)n_in; (void)out_size;
    const float* x    = (const float*)d_in[0];
    const float* embW = (const float*)d_in[1];
    const float* embB = (const float*)d_in[2];
    const float* nu   = (const float*)d_in[3];
    const float* th   = (const float*)d_in[4];
    const float* gl   = (const float*)d_in[5];
    const float* Bre  = (const float*)d_in[6];
    const float* Bim  = (const float*)d_in[7];
    const float* Cre  = (const float*)d_in[8];
    const float* Cim  = (const float*)d_in[9];
    const float* Dm   = (const float*)d_in[10];
    const float* Wh   = (const float*)d_in[11];
    const float* bh   = (const float*)d_in[12];
    const float* Wo   = (const float*)d_in[13];
    const float* bo   = (const float*)d_in[14];
    const float* outW = (const float*)d_in[15];
    const float* outB = (const float*)d_in[16];
    float* out = (float*)d_out;

    float *hf, *yf, *sre, *sim, *eg;
    cudaGetSymbolAddress((void**)&hf,  g_h);
    cudaGetSymbolAddress((void**)&yf,  g_y);
    cudaGetSymbolAddress((void**)&sre, g_sre);
    cudaGetSymbolAddress((void**)&sim, g_sim);
    cudaGetSymbolAddress((void**)&eg,  g_eg);

    uint16_t *xh,*xl,*eWh,*eWl,*Brh,*Brl,*Bih,*Bil,*Crh,*Crl,*nCih,*nCil;
    uint16_t *Whh,*Whl,*Woh,*Wol,*oWh,*oWl;
    uint16_t *hh,*hl,*yh,*yl,*srh,*srl,*sih,*sil,*zh,*zl;
    cudaGetSymbolAddress((void**)&xh,  g_x_h);  cudaGetSymbolAddress((void**)&xl,  g_x_l);
    cudaGetSymbolAddress((void**)&eWh, g_eW_h); cudaGetSymbolAddress((void**)&eWl, g_eW_l);
    cudaGetSymbolAddress((void**)&Brh, g_Br_h); cudaGetSymbolAddress((void**)&Brl, g_Br_l);
    cudaGetSymbolAddress((void**)&Bih, g_Bi_h); cudaGetSymbolAddress((void**)&Bil, g_Bi_l);
    cudaGetSymbolAddress((void**)&Crh, g_Cr_h); cudaGetSymbolAddress((void**)&Crl, g_Cr_l);
    cudaGetSymbolAddress((void**)&nCih,g_nCi_h);cudaGetSymbolAddress((void**)&nCil,g_nCi_l);
    cudaGetSymbolAddress((void**)&Whh, g_Wh_h); cudaGetSymbolAddress((void**)&Whl, g_Wh_l);
    cudaGetSymbolAddress((void**)&Woh, g_Wo_h); cudaGetSymbolAddress((void**)&Wol, g_Wo_l);
    cudaGetSymbolAddress((void**)&oWh, g_oW_h); cudaGetSymbolAddress((void**)&oWl, g_oW_l);
    cudaGetSymbolAddress((void**)&hh,  g_h_h);  cudaGetSymbolAddress((void**)&hl,  g_h_l);
    cudaGetSymbolAddress((void**)&yh,  g_y_h);  cudaGetSymbolAddress((void**)&yl,  g_y_l);
    cudaGetSymbolAddress((void**)&srh, g_sr_h); cudaGetSymbolAddress((void**)&srl, g_sr_l);
    cudaGetSymbolAddress((void**)&sih, g_si_h); cudaGetSymbolAddress((void**)&sil, g_si_l);
    cudaGetSymbolAddress((void**)&zh,  g_z_h);  cudaGetSymbolAddress((void**)&zl,  g_z_l);

    cudaFuncSetAttribute(mma_gemm<0,false,true ,true >, cudaFuncAttributeMaxDynamicSharedMemorySize, SMEM_BYTES);
    cudaFuncSetAttribute(mma_gemm<3,false,true ,false>, cudaFuncAttributeMaxDynamicSharedMemorySize, SMEM_BYTES);
    cudaFuncSetAttribute(mma_gemm<4,true ,true ,true >, cudaFuncAttributeMaxDynamicSharedMemorySize, SMEM_BYTES);
    cudaFuncSetAttribute(mma_gemm<1,false,false,true >, cudaFuncAttributeMaxDynamicSharedMemorySize, SMEM_BYTES);
    cudaFuncSetAttribute(mma_gemm<2,false,true ,true >, cudaFuncAttributeMaxDynamicSharedMemorySize, SMEM_BYTES);
    cudaFuncSetAttribute(mma_gemm<0,false,true ,false>, cudaFuncAttributeMaxDynamicSharedMemorySize, SMEM_BYTES);

    prep_kernel<<<NL, STATE>>>(nu, th, gl);

    // split inputs & weights to bf16 hi/lo
    cvt_split<<<(BL*INDIM)/256, 256>>>(x, xh, xl, 1.f);
    cvt_split<<<(HID*INDIM)/256, 256>>>(embW, eWh, eWl, 1.f);
    cvt_split<<<(NL*STATE*HID)/256, 256>>>(Bre, Brh, Brl, 1.f);
    cvt_split<<<(NL*STATE*HID)/256, 256>>>(Bim, Bih, Bil, 1.f);
    cvt_split<<<(NL*HID*STATE)/256, 256>>>(Cre, Crh, Crl, 1.f);
    cvt_split<<<(NL*HID*STATE)/256, 256>>>(Cim, nCih, nCil, -1.f);
    cvt_split<<<(NL*MLPD*STATE)/256, 256>>>(Wh, Whh, Whl, 1.f);
    cvt_split<<<(NL*HID*MLPD)/256, 256>>>(Wo, Woh, Wol, 1.f);
    cvt_split<<<(OUTD*HID)/256, 256>>>(outW, oWh, oWl, 1.f);

    const dim3 blk(256);

    // embedding: h = x @ embW^T + embB          (BL x 256, K=64)
    mma_gemm<0,false,true,true><<<dim3(HID/128, BL/128), blk, SMEM_BYTES>>>(
        xh, xl, eWh, eWl, nullptr, nullptr, nullptr, nullptr,
        hf, hh, hl, HID, INDIM, embB, nullptr, nullptr);

    for (int l = 0; l < NL; ++l) {
        const size_t bw = (size_t)l * STATE * HID;
        const size_t cw = (size_t)l * HID * STATE;
        const size_t ww = (size_t)l * MLPD * STATE;
        const size_t ow = (size_t)l * HID * MLPD;

        // Bu = (h @ B^T) * exp(gamma)[col]  -> fp32 sre/sim (scan input)
        mma_gemm<3,false,true,false><<<dim3(STATE/128, BL/128), blk, SMEM_BYTES>>>(
            hh, hl, Brh + bw, Brl + bw, nullptr, nullptr, nullptr, nullptr,
            sre, nullptr, nullptr, STATE, HID, nullptr, eg + l*STATE, nullptr);
        mma_gemm<3,false,true,false><<<dim3(STATE/128, BL/128), blk, SMEM_BYTES>>>(
            hh, hl, Bih + bw, Bil + bw, nullptr, nullptr, nullptr, nullptr,
            sim, nullptr, nullptr, STATE, HID, nullptr, eg + l*STATE, nullptr);

        // diagonal complex scan; pass3 emits bf16 hi/lo states
        scan_pass1<<<dim3(NC, BATCHN), STATE>>>(l);
        scan_pass2<<<BATCHN, STATE>>>(l, nu, th);
        scan_pass3<<<dim3(NC, BATCHN), STATE>>>(l);

        // y = sre@Cre^T + sim@(-Cim)^T + D[col]*h
        mma_gemm<4,true,true,true><<<dim3(HID/128, BL/128), blk, SMEM_BYTES>>>(
            srh, srl, Crh + cw, Crl + cw, sih, sil, nCih + cw, nCil + cw,
            yf, yh, yl, HID, STATE, nullptr, Dm + l*HID, hf);

        // z = gelu(y @ Wh^T + bh)   (bf16 only)
        mma_gemm<1,false,false,true><<<dim3(MLPD/128, BL/128), blk, SMEM_BYTES>>>(
            yh, yl, Whh + ww, Whl + ww, nullptr, nullptr, nullptr, nullptr,
            nullptr, zh, zl, MLPD, STATE, bh + l*MLPD, nullptr, nullptr);

        // h = z @ Wo^T + bo + y
        mma_gemm<2,false,true,true><<<dim3(HID/128, BL/128), blk, SMEM_BYTES>>>(
            zh, zl, Woh + ow, Wol + ow, nullptr, nullptr, nullptr, nullptr,
            hf, hh, hl, HID, MLPD, bo + l*HID, nullptr, yf);
    }

    // out = h @ outW^T + outB
    mma_gemm<0,false,true,false><<<dim3(OUTD/128, BL/128), blk, SMEM_BYTES>>>(
        hh, hl, oWh, oWl, nullptr, nullptr, nullptr, nullptr,
        out, nullptr, nullptr, OUTD, HID, outB, nullptr, nullptr);
}

// round 9
// speedup vs baseline: 1.1904x; 1.1904x over previous
#include <cuda_runtime.h>
#include <math.h>
#include <stdint.h>

// ---------------- problem constants ----------------
#define BATCHN  16
#define LSEQ    2048
#define INDIM   64
#define HID     256
#define STATE   256
#define MLPD    1024
#define OUTD    128
#define NL      4
#define BL      (BATCHN * LSEQ)      // 32768 rows
#define CL      128                  // scan chunk length
#define NC      (LSEQ / CL)          // 16 chunks

// smem tile layout (bytes): rows padded to 80B — conflict-free ldmatrix
// CTA tile: 128(M) x 64(N), K chunk 32; 3-stage pipeline
#define LDS_ROW   80
#define T_AH      0
#define T_AL      10240              // 128 rows * 80
#define T_BH      20480
#define T_BL      25600              // 64 rows * 80
#define STAGE_B   30720
#define SMEM_BYTES (3 * STAGE_B)     // 92160 -> 2 CTAs/SM (184 KB)

// ---------------- device scratch (static, no allocations) ----------------
__device__ float g_h  [BL * HID];
__device__ float g_y  [BL * HID];
__device__ float g_sre[BL * STATE];
__device__ float g_sim[BL * STATE];
__device__ float g_z  [BL * MLPD];
__device__ float g_cre[BATCHN * NC * STATE];
__device__ float g_cim[BATCHN * NC * STATE];
__device__ float g_ire[BATCHN * NC * STATE];
__device__ float g_iim[BATCHN * NC * STATE];
__device__ float g_lamre[NL * STATE];
__device__ float g_lamim[NL * STATE];
__device__ float g_eg   [NL * STATE];
__device__ float g_negCim[NL * HID * STATE];
__device__ float g_Bpack[NL * 2 * STATE * HID];   // [Bre;Bim] stacked along N

// ---------------- PTX helpers ----------------
__device__ __forceinline__ uint32_t smem_u32(const void* p) {
    uint32_t a;
    asm("{ .reg .u64 t; cvta.to.shared.u64 t, %1; cvt.u32.u64 %0, t; }"
        : "=r"(a) : "l"(p));
    return a;
}
// pack two fp32 -> bf16x2 (x in low half, y in high half)
__device__ __forceinline__ uint32_t cvt2(float x, float y) {
    uint32_t r;
    asm("cvt.rn.bf16x2.f32 %0, %1, %2;" : "=r"(r) : "f"(y), "f"(x));
    return r;
}
__device__ __forceinline__ float lo_of(uint32_t h) { return __uint_as_float(h << 16); }
__device__ __forceinline__ float hi_of(uint32_t h) { return __uint_as_float(h & 0xFFFF0000u); }
__device__ __forceinline__ void sts64(uint32_t a, uint32_t x, uint32_t y) {
    asm volatile("st.shared.v2.b32 [%0], {%1, %2};" :: "r"(a), "r"(x), "r"(y) : "memory");
}
#define LDSM4(r0, r1, r2, r3, addr) \
    asm volatile("ldmatrix.sync.aligned.m8n8.x4.shared.b16 {%0,%1,%2,%3}, [%4];" \
                 : "=r"(r0), "=r"(r1), "=r"(r2), "=r"(r3) : "r"(addr))
#define MMA_BF16(d, a, b) \
    asm volatile("mma.sync.aligned.m16n8k16.row.col.f32.bf16.bf16.f32 " \
                 "{%0,%1,%2,%3},{%4,%5,%6,%7},{%8,%9},{%0,%1,%2,%3};" \
                 : "+f"((d)[0]), "+f"((d)[1]), "+f"((d)[2]), "+f"((d)[3]) \
                 : "r"((a)[0]), "r"((a)[1]), "r"((a)[2]), "r"((a)[3]), \
                   "r"((b)[0]), "r"((b)[1]))

// ---------------- small prep kernels ----------------
__global__ void prep_kernel(const float* __restrict__ nu,
                            const float* __restrict__ th,
                            const float* __restrict__ gl) {
    const int l = blockIdx.x, s = threadIdx.x;
    const int idx = l * STATE + s;
    const float enu = expf(nu[idx]);
    const float eth = expf(th[idx]);
    const float mag = expf(-enu);
    g_lamre[idx] = mag * cosf(eth);
    g_lamim[idx] = mag * sinf(eth);
    g_eg[idx]    = expf(gl[idx]);
}

__global__ void neg_kernel(const float* __restrict__ Cim) {
    const int i = blockIdx.x * 256 + threadIdx.x;
    g_negCim[i] = -Cim[i];
}

// pack [Bre;Bim] along the N dimension per layer: dst[l][row][k], rows 0..255=re,
// 256..511=im
__global__ void pack_kernel(const float* __restrict__ Bre,
                            const float* __restrict__ Bim) {
    const int i = blockIdx.x * 256 + threadIdx.x;       // over NL*STATE*HID
    const int l = i / (STATE * HID);
    const int r = (i / HID) % STATE;
    const int k = i % HID;
    g_Bpack[((size_t)l * 2 * STATE + r) * HID + k]         = Bre[i];
    g_Bpack[((size_t)l * 2 * STATE + STATE + r) * HID + k] = Bim[i];
}

// ---------------- chunked complex diagonal scan ----------------
// pass1: read-only local scan -> chunk carries
__global__ void scan_pass1(int l) {
    const int s = threadIdx.x, c = blockIdx.x, b = blockIdx.y;
    const float lr = g_lamre[l * STATE + s];
    const float li = g_lamim[l * STATE + s];
    size_t idx = ((size_t)(b * LSEQ + c * CL)) * STATE + s;
    float ar = 0.f, ai = 0.f;
    for (int t = 0; t < CL; ++t, idx += STATE) {
        const float br = g_sre[idx], bi = g_sim[idx];
        const float nr = fmaf(lr, ar, fmaf(-li, ai, br));
        const float ni = fmaf(lr, ai, fmaf( li, ar, bi));
        ar = nr; ai = ni;
    }
    const int ci = (b * NC + c) * STATE + s;
    g_cre[ci] = ar; g_cim[ci] = ai;
}

__global__ void scan_pass2(int l, const float* __restrict__ nu,
                           const float* __restrict__ th) {
    const int s = threadIdx.x, b = blockIdx.x;
    const float enu = expf(nu[l * STATE + s]);
    const float eth = expf(th[l * STATE + s]);
    const float r   = expf(-(float)CL * enu);
    const float ang = (float)CL * eth;
    const float Ar = r * cosf(ang), Ai = r * sinf(ang);
    float pr = 0.f, pi = 0.f;
    for (int c = 0; c < NC; ++c) {
        const int ci = (b * NC + c) * STATE + s;
        g_ire[ci] = pr; g_iim[ci] = pi;
        const float cr = g_cre[ci], cii = g_cim[ci];
        const float nr = fmaf(Ar, pr, fmaf(-Ai, pi, cr));
        const float ni = fmaf(Ar, pi, fmaf( Ai, pr, cii));
        pr = nr; pi = ni;
    }
}

// pass3: recurrence seeded with incoming prefix; writes final states
__global__ void scan_pass3(int l) {
    const int s = threadIdx.x, c = blockIdx.x, b = blockIdx.y;
    const int ci = (b * NC + c) * STATE + s;
    const float lr = g_lamre[l * STATE + s];
    const float li = g_lamim[l * STATE + s];
    float ar = g_ire[ci], ai = g_iim[ci];   // zero for c==0
    size_t idx = ((size_t)(b * LSEQ + c * CL)) * STATE + s;
    for (int t = 0; t < CL; ++t, idx += STATE) {
        const float br = g_sre[idx], bi = g_sim[idx];
        const float nr = fmaf(lr, ar, fmaf(-li, ai, br));
        const float ni = fmaf(lr, ai, fmaf( li, ar, bi));
        ar = nr; ai = ni;
        g_sre[idx] = ar; g_sim[idx] = ai;
    }
}

// ---------------- stage store: fp32 float4 -> hi/lo bf16 smem ----------------
// A: 128 rows x 32 cols (1024 float4 slots), B: 64 rows x 32 cols (512 slots)
__device__ __forceinline__ void store_stage(uint32_t base, const float4* pA,
                                            const float4* pB, int tid)
{
#pragma unroll
    for (int i = 0; i < 4; ++i) {
        const int slot = i * 256 + tid;
        const int r = slot >> 3, c4 = slot & 7;
        const uint32_t off = (uint32_t)(r * LDS_ROW + c4 * 8);
        const float4 f = pA[i];
        const uint32_t h0 = cvt2(f.x, f.y), h1 = cvt2(f.z, f.w);
        const uint32_t l0 = cvt2(f.x - lo_of(h0), f.y - hi_of(h0));
        const uint32_t l1 = cvt2(f.z - lo_of(h1), f.w - hi_of(h1));
        sts64(base + T_AH + off, h0, h1);
        sts64(base + T_AL + off, l0, l1);
    }
#pragma unroll
    for (int i = 0; i < 2; ++i) {
        const int slot = i * 256 + tid;
        const int r = slot >> 3, c4 = slot & 7;
        const uint32_t off = (uint32_t)(r * LDS_ROW + c4 * 8);
        const float4 f = pB[i];
        const uint32_t h0 = cvt2(f.x, f.y), h1 = cvt2(f.z, f.w);
        const uint32_t l0 = cvt2(f.x - lo_of(h0), f.y - hi_of(h0));
        const uint32_t l1 = cvt2(f.z - lo_of(h1), f.w - hi_of(h1));
        sts64(base + T_BH + off, h0, h1);
        sts64(base + T_BL + off, l0, l1);
    }
}

// ---------------- bf16x3 warp-MMA GEMM: C = A(MxK) @ W(NxK)^T + epilogue -----
// CTA tile 128x64; 8 warps in 4(M) x 2(N); warp tile 32x32.
// 3-stage smem pipeline, ONE __syncthreads per k-chunk.
// EPI: 0=+bias 1=gelu(x+bias) 2=+bias+res 3=*scale[col] 4=+scale[col]*res
//      5=*scale[col%STATE], split output: cols<STATE -> Cout, else -> out2
//        (both with row stride STATE; scale/res params reused: res = out2)
// DUAL: accumulate a second (A2, W2) product with the same K.
template <int EPI, bool DUAL>
__global__ void __launch_bounds__(256, 2)
mma_gemm(const float* __restrict__ A,  const float* __restrict__ W,
         const float* __restrict__ A2, const float* __restrict__ W2,
         float* __restrict__ Cout, int N, int K,
         const float* __restrict__ bias, const float* __restrict__ scale,
         const float* __restrict__ res)
{
    extern __shared__ char smem[];
    const uint32_t sb = smem_u32(smem);
    const int tid  = threadIdx.x;
    const int lane = tid & 31, wid = tid >> 5;
    const int wm = wid & 3, wn = wid >> 2;          // warp grid 4(M) x 2(N)
    const int row0 = blockIdx.y * 128, col0 = blockIdx.x * 64;

    float acc[2][4][4];
#pragma unroll
    for (int mt = 0; mt < 2; ++mt)
#pragma unroll
        for (int nt = 0; nt < 4; ++nt)
#pragma unroll
            for (int e = 0; e < 4; ++e) acc[mt][nt][e] = 0.f;

    const int KC   = K >> 5;
    const int CTOT = DUAL ? 2 * KC : KC;

    // ldmatrix per-lane offsets (bytes within a hi/lo tile)
    const uint32_t aOff = (uint32_t)((wm * 32 + (lane & 15)) * LDS_ROW + ((lane >> 4) << 4));
    const uint32_t bOff = (uint32_t)((wn * 32 + (((lane >> 4) << 3) | (lane & 7))) * LDS_ROW
                                     + (((lane >> 3) & 1) << 4));

    float4 pA[4], pB[2];

    // register-load of chunk c
    auto ldchunk = [&](int c) {
        const int pass = (DUAL && c >= KC) ? 1 : 0;
        const int k0 = (c - (pass ? KC : 0)) << 5;
        const float* Ap = pass ? A2 : A;
        const float* Wp = pass ? W2 : W;
#pragma unroll
        for (int i = 0; i < 4; ++i) {
            const int slot = i * 256 + tid, r = slot >> 3, c4 = slot & 7;
            pA[i] = *(const float4*)(Ap + (size_t)(row0 + r) * K + k0 + c4 * 4);
        }
#pragma unroll
        for (int i = 0; i < 2; ++i) {
            const int slot = i * 256 + tid, r = slot >> 3, c4 = slot & 7;
            pB[i] = *(const float4*)(Wp + (size_t)(col0 + r) * K + k0 + c4 * 4);
        }
    };

    // prologue: chunk 0 staged, chunk 1 in registers
    ldchunk(0);
    store_stage(sb, pA, pB, tid);
    if (CTOT > 1) ldchunk(1);
    __syncthreads();

    int bufC = 0, bufS = 1;                         // compute buf, store buf
    for (int c = 0; c < CTOT; ++c) {
        if (c + 1 < CTOT)
            store_stage(sb + (uint32_t)bufS * STAGE_B, pA, pB, tid);
        if (c + 2 < CTOT) ldchunk(c + 2);

        const uint32_t st = sb + (uint32_t)bufC * STAGE_B;
#pragma unroll
        for (int ks = 0; ks < 2; ++ks) {
            uint32_t ah[2][4], al[2][4], bh[4][2], bl[4][2];
            const uint32_t kb = (uint32_t)(ks * 32);
#pragma unroll
            for (int mt = 0; mt < 2; ++mt) {
                const uint32_t ad = st + aOff + (uint32_t)(mt * 16 * LDS_ROW) + kb;
                LDSM4(ah[mt][0], ah[mt][1], ah[mt][2], ah[mt][3], ad + T_AH);
                LDSM4(al[mt][0], al[mt][1], al[mt][2], al[mt][3], ad + T_AL);
            }
#pragma unroll
            for (int np = 0; np < 2; ++np) {
                const uint32_t bd = st + bOff + (uint32_t)(np * 16 * LDS_ROW) + kb;
                LDSM4(bh[np*2][0], bh[np*2][1], bh[np*2+1][0], bh[np*2+1][1], bd + T_BH);
                LDSM4(bl[np*2][0], bl[np*2][1], bl[np*2+1][0], bl[np*2+1][1], bd + T_BL);
            }
#pragma unroll
            for (int mt = 0; mt < 2; ++mt)
#pragma unroll
                for (int nt = 0; nt < 4; ++nt) {
                    MMA_BF16(acc[mt][nt], ah[mt], bh[nt]);
                    MMA_BF16(acc[mt][nt], al[mt], bh[nt]);
                    MMA_BF16(acc[mt][nt], ah[mt], bl[nt]);
                }
        }
        __syncthreads();
        bufC = (bufC == 2) ? 0 : bufC + 1;
        bufS = (bufS == 2) ? 0 : bufS + 1;
    }

    // ---- epilogue: write fragments with fused op ----
    // EPI5: whole CTA lies in one output half (64 | STATE)
    float* out5 = (EPI == 5 && col0 >= STATE) ? (float*)res : Cout;
    const int cbase5 = (EPI == 5 && col0 >= STATE) ? STATE : 0;

#pragma unroll
    for (int mt = 0; mt < 2; ++mt) {
#pragma unroll
        for (int nt = 0; nt < 4; ++nt) {
            const int rA = row0 + wm * 32 + mt * 16 + (lane >> 2);
            const int cc = col0 + wn * 32 + nt * 8 + (lane & 3) * 2;
#pragma unroll
            for (int half = 0; half < 2; ++half) {
                const int r = rA + half * 8;
                float v0 = acc[mt][nt][half * 2 + 0];
                float v1 = acc[mt][nt][half * 2 + 1];
                if (EPI == 5) {
                    const int c5 = cc - cbase5;
                    const size_t go5 = (size_t)r * STATE + c5;
                    v0 *= scale[c5]; v1 *= scale[c5 + 1];
                    *(float2*)&out5[go5] = make_float2(v0, v1);
                    continue;
                }
                const size_t go = (size_t)r * N + cc;
                if (EPI == 0) { v0 += bias[cc]; v1 += bias[cc + 1]; }
                if (EPI == 1) {
                    const float t0 = v0 + bias[cc], t1 = v1 + bias[cc + 1];
                    v0 = 0.5f * t0 * (1.0f + erff(t0 * 0.7071067811865476f));
                    v1 = 0.5f * t1 * (1.0f + erff(t1 * 0.7071067811865476f));
                }
                if (EPI == 2) { v0 += bias[cc]     + res[go];
                                v1 += bias[cc + 1] + res[go + 1]; }
                if (EPI == 3) { v0 *= scale[cc]; v1 *= scale[cc + 1]; }
                if (EPI == 4) { v0 = fmaf(scale[cc],     res[go],     v0);
                                v1 = fmaf(scale[cc + 1], res[go + 1], v1); }
                *(float2*)&Cout[go] = make_float2(v0, v1);
            }
        }
    }
}

// ---------------- launch ----------------
extern "C" void kernel_launch(void* const* d_in, const int* in_sizes, int n_in,
                              void* d_out, int out_size)
{
    (void)in_sizes; (void)n_in; (void)out_size;
    const float* x    = (const float*)d_in[0];
    const float* embW = (const float*)d_in[1];
    const float* embB = (const float*)d_in[2];
    const float* nu   = (const float*)d_in[3];
    const float* th   = (const float*)d_in[4];
    const float* gl   = (const float*)d_in[5];
    const float* Bre  = (const float*)d_in[6];
    const float* Bim  = (const float*)d_in[7];
    const float* Cre  = (const float*)d_in[8];
    const float* Cim  = (const float*)d_in[9];
    const float* Dm   = (const float*)d_in[10];
    const float* Wh   = (const float*)d_in[11];
    const float* bh   = (const float*)d_in[12];
    const float* Wo   = (const float*)d_in[13];
    const float* bo   = (const float*)d_in[14];
    const float* outW = (const float*)d_in[15];
    const float* outB = (const float*)d_in[16];
    float* out = (float*)d_out;

    float *h, *y, *sre, *sim, *z, *eg, *negc, *bpack;
    cudaGetSymbolAddress((void**)&h,    g_h);
    cudaGetSymbolAddress((void**)&y,    g_y);
    cudaGetSymbolAddress((void**)&sre,  g_sre);
    cudaGetSymbolAddress((void**)&sim,  g_sim);
    cudaGetSymbolAddress((void**)&z,    g_z);
    cudaGetSymbolAddress((void**)&eg,   g_eg);
    cudaGetSymbolAddress((void**)&negc, g_negCim);
    cudaGetSymbolAddress((void**)&bpack, g_Bpack);

    cudaFuncSetAttribute(mma_gemm<0, false>, cudaFuncAttributeMaxDynamicSharedMemorySize, SMEM_BYTES);
    cudaFuncSetAttribute(mma_gemm<1, false>, cudaFuncAttributeMaxDynamicSharedMemorySize, SMEM_BYTES);
    cudaFuncSetAttribute(mma_gemm<2, false>, cudaFuncAttributeMaxDynamicSharedMemorySize, SMEM_BYTES);
    cudaFuncSetAttribute(mma_gemm<4, true >, cudaFuncAttributeMaxDynamicSharedMemorySize, SMEM_BYTES);
    cudaFuncSetAttribute(mma_gemm<5, false>, cudaFuncAttributeMaxDynamicSharedMemorySize, SMEM_BYTES);

    prep_kernel<<<NL, STATE>>>(nu, th, gl);
    neg_kernel<<<(NL * HID * STATE) / 256, 256>>>(Cim);
    pack_kernel<<<(NL * STATE * HID) / 256, 256>>>(Bre, Bim);

    const dim3 blk(256);

    // embedding: h = x @ embW^T + embB          (BL x 256, K=64)
    mma_gemm<0, false><<<dim3(HID / 64, BL / 128), blk, SMEM_BYTES>>>(
        x, embW, nullptr, nullptr, h, HID, INDIM, embB, nullptr, nullptr);

    for (int l = 0; l < NL; ++l) {
        // Bu(re|im) fused: (h @ [Bre;Bim]^T) * eg[col%256] -> sre / sim
        mma_gemm<5, false><<<dim3((2 * STATE) / 64, BL / 128), blk, SMEM_BYTES>>>(
            h, bpack + (size_t)l * 2 * STATE * HID, nullptr, nullptr, sre,
            2 * STATE, HID, nullptr, eg + l * STATE, sim);

        // diagonal complex scan
        scan_pass1<<<dim3(NC, BATCHN), STATE>>>(l);
        scan_pass2<<<BATCHN, STATE>>>(l, nu, th);
        scan_pass3<<<dim3(NC, BATCHN), STATE>>>(l);

        // y = sre@Cre^T + sim@(-Cim)^T + D[col]*h
        mma_gemm<4, true><<<dim3(HID / 64, BL / 128), blk, SMEM_BYTES>>>(
            sre, Cre + (size_t)l * HID * STATE,
            sim, negc + (size_t)l * HID * STATE, y,
            HID, STATE, nullptr, Dm + l * HID, h);

        // z = gelu(y @ Wh^T + bh)               (BL x 1024, K=256)
        mma_gemm<1, false><<<dim3(MLPD / 64, BL / 128), blk, SMEM_BYTES>>>(
            y, Wh + (size_t)l * MLPD * STATE, nullptr, nullptr, z,
            MLPD, STATE, bh + l * MLPD, nullptr, nullptr);

        // h = z @ Wo^T + bo + y                 (BL x 256, K=1024)
        mma_gemm<2, false><<<dim3(HID / 64, BL / 128), blk, SMEM_BYTES>>>(
            z, Wo + (size_t)l * HID * MLPD, nullptr, nullptr, h,
            HID, MLPD, bo + l * HID, nullptr, y);
    }

    // out = h @ outW^T + outB                   (BL x 128, K=256)
    mma_gemm<0, false><<<dim3(OUTD / 64, BL / 128), blk, SMEM_BYTES>>>(
        h, outW, nullptr, nullptr, out, OUTD, HID, outB, nullptr, nullptr);
}